// round 3
// baseline (speedup 1.0000x reference)
#include <cuda_runtime.h>
#include <cstdint>

// ---------------- problem constants ----------------
#define Bdim 8
#define Cdim 64
#define Hdim 256
#define Wdim 256
#define HW   65536              // Hdim*Wdim
#define KW   9                  // 3x3
#define NW   36864              // 64*64*3*3 weight elements
#define TW   128                // conv tile width (pixels per block along x)

// ---------------- device scratch (no allocs allowed) ----------------
__device__ signed char g_q8[(size_t)Bdim * HW * Cdim];   // NHWC int8 quantized activations (33.5 MB)
__device__ float       g_invs[Bdim * HW];                // per-pixel 1/s_act
__device__ signed char g_w8[KW * 64 * 64];               // ternary weights, layout [k][co][ci]
__device__ float       g_wscale;                         // 1/s_w = mean|W| (clamped)

// =====================================================================
// Kernel 1: ternary weight quantization (single block)
//   s_w = 1/max(mean|W|,1e-8); t = clip(rint(s_w*W),-1,1); store [k][co][ci]
// =====================================================================
__global__ void __launch_bounds__(1024) wquant_kernel(const float* __restrict__ W) {
    __shared__ float red[1024];
    __shared__ float s_sw;
    int tid = threadIdx.x;

    float s = 0.f;
    for (int i = tid; i < NW; i += 1024) s += fabsf(W[i]);
    red[tid] = s;
    __syncthreads();
    for (int off = 512; off > 0; off >>= 1) {
        if (tid < off) red[tid] += red[tid + off];
        __syncthreads();
    }
    if (tid == 0) {
        float mean = red[0] * (1.0f / (float)NW);
        float sw = 1.0f / fmaxf(mean, 1e-8f);
        s_sw = sw;
        g_wscale = 1.0f / sw;
    }
    __syncthreads();
    float sw = s_sw;

    for (int i = tid; i < NW; i += 1024) {
        float t = rintf(sw * W[i]);
        t = fminf(fmaxf(t, -1.0f), 1.0f);
        int k  = i % 9;          // OIHW: i = (co*64+ci)*9 + k
        int cc = i / 9;
        int ci = cc & 63;
        int co = cc >> 6;
        g_w8[k * 4096 + co * 64 + ci] = (signed char)t;
    }
}

// =====================================================================
// Kernel 2: per-pixel LayerNorm + int8 fake-quant (single pass,
// channel values cached in registers). Warp = 32 consecutive pixels ->
// every channel load is a fully coalesced 128B line.
// =====================================================================
__global__ void __launch_bounds__(256) normquant_kernel(const float* __restrict__ x) {
    int gp = blockIdx.x * 256 + threadIdx.x;        // global pixel id, 0..B*HW-1
    int b  = gp >> 16;
    int p  = gp & (HW - 1);
    const float* xb = x + (size_t)b * Cdim * HW + p;

    float v[64];
    float sum = 0.f;
#pragma unroll
    for (int c = 0; c < 64; c++) { v[c] = xb[(size_t)c * HW]; sum += v[c]; }
    float mu = sum * (1.0f / 64.0f);

    float sq = 0.f, mx = 0.f;
#pragma unroll
    for (int c = 0; c < 64; c++) {
        float d = v[c] - mu;
        v[c] = d;
        sq += d * d;
        mx = fmaxf(mx, fabsf(d));
    }
    float var  = sq * (1.0f / 64.0f);
    float r    = 1.0f / sqrtf(var + 1e-8f);
    float ymax = r * mx;                            // max|r*(x-mu)|
    float s    = 127.0f / fmaxf(ymax, 1e-8f);
    float sr   = s * r;

    int wbuf[16];
#pragma unroll
    for (int c4 = 0; c4 < 16; c4++) {
        int packed = 0;
#pragma unroll
        for (int j = 0; j < 4; j++) {
            float t = rintf(sr * v[c4 * 4 + j]);    // rint = round-half-even, matches jnp.round
            t = fminf(fmaxf(t, -128.f), 127.f);
            int q = (int)t;
            packed |= (q & 0xFF) << (8 * j);
        }
        wbuf[c4] = packed;
    }
    int4* dst = (int4*)(g_q8 + (size_t)gp * 64);
    dst[0] = make_int4(wbuf[0],  wbuf[1],  wbuf[2],  wbuf[3]);
    dst[1] = make_int4(wbuf[4],  wbuf[5],  wbuf[6],  wbuf[7]);
    dst[2] = make_int4(wbuf[8],  wbuf[9],  wbuf[10], wbuf[11]);
    dst[3] = make_int4(wbuf[12], wbuf[13], wbuf[14], wbuf[15]);
    g_invs[gp] = 1.0f / s;
}

// =====================================================================
// Kernel 3: 3x3 conv via exact int8 dp4a + per-tap fp32 scale.
// Block: 256 threads, tile = 1 row x 128 px x all 64 co.
// Thread = (co = tid&63, 32-px group). Warp lanes share the pixel group ->
// q/invs smem loads are warp-broadcast (conflict free); w loads amortized.
// Output staged through padded smem so NCHW global stores are coalesced.
// =====================================================================
#define Q_TILE_INT4   1560      // 3 rows * 130 px * 4 int4
#define SMEM_W_OFF    0         // 36864 B
#define SMEM_Q_OFF    36864     // 24960 B
#define SMEM_INV_OFF  61824     // 1584 B
#define SMEM_OUT_OFF  36864     // 64*129*4 = 33024 B (overlays Q+INV after compute)
#define SMEM_BYTES    69888

__global__ void __launch_bounds__(256) conv_kernel(const float* __restrict__ bias,
                                                   float* __restrict__ out) {
    extern __shared__ char smem[];
    char*  w_s   = smem + SMEM_W_OFF;
    char*  q_s   = smem + SMEM_Q_OFF;
    float* inv_s = (float*)(smem + SMEM_INV_OFF);
    float* out_s = (float*)(smem + SMEM_OUT_OFF);

    int tid = threadIdx.x;
    int b = blockIdx.z, y = blockIdx.y, x0 = blockIdx.x * TW;

    // ---- load ternary weights (L2-resident, 36.9 KB) ----
    {
        const int4* gw = (const int4*)g_w8;
        int4* dw = (int4*)w_s;
        for (int i = tid; i < 2304; i += 256) dw[i] = gw[i];
    }
    // ---- load q tile: 3 rows x [x0-1, x0+TW] x 64ch, zero-padded ----
    {
        int4* dq = (int4*)q_s;
        for (int i = tid; i < Q_TILE_INT4; i += 256) {
            int rr  = i / 520;
            int rem = i - rr * 520;         // = px*4 + c
            int px  = rem >> 2;
            int c   = rem & 3;
            int yy = y + rr - 1, xx = x0 + px - 1;
            int4 v = make_int4(0, 0, 0, 0);
            if ((unsigned)yy < 256u && (unsigned)xx < 256u) {
                int gp = (b << 16) + (yy << 8) + xx;
                v = ((const int4*)g_q8)[(size_t)gp * 4 + c];
            }
            dq[i] = v;
        }
        for (int i = tid; i < 390; i += 256) {
            int rr = i / 130, px = i - rr * 130;
            int yy = y + rr - 1, xx = x0 + px - 1;
            float v = 0.f;
            if ((unsigned)yy < 256u && (unsigned)xx < 256u)
                v = g_invs[(b << 16) + (yy << 8) + xx];
            inv_s[rr * 132 + px] = v;
        }
    }
    __syncthreads();

    int co  = tid & 63;
    int pxb = (tid >> 6) * 32;

    float acc[32];
#pragma unroll
    for (int p = 0; p < 32; p++) acc[p] = 0.f;

    const int4* wq = ((const int4*)w_s) + co * 4;

#pragma unroll 1
    for (int k = 0; k < 9; k++) {
        int rr = k / 3;
        int dx = k - rr * 3;
        int4 w0 = wq[k * 256 + 0];
        int4 w1 = wq[k * 256 + 1];
        int4 w2 = wq[k * 256 + 2];
        int4 w3 = wq[k * 256 + 3];
        const int4*  qrow = ((const int4*)q_s) + rr * 520 + pxb * 4;
        const float* irow = inv_s + rr * 132 + pxb;
#pragma unroll
        for (int p = 0; p < 32; p++) {
            int sx = p + dx;
            int4 q0 = qrow[sx * 4 + 0];
            int4 q1 = qrow[sx * 4 + 1];
            int4 q2 = qrow[sx * 4 + 2];
            int4 q3 = qrow[sx * 4 + 3];
            int d0 = 0, d1 = 0, d2 = 0, d3 = 0;
            d0 = __dp4a(q0.x, w0.x, d0); d0 = __dp4a(q0.y, w0.y, d0);
            d0 = __dp4a(q0.z, w0.z, d0); d0 = __dp4a(q0.w, w0.w, d0);
            d1 = __dp4a(q1.x, w1.x, d1); d1 = __dp4a(q1.y, w1.y, d1);
            d1 = __dp4a(q1.z, w1.z, d1); d1 = __dp4a(q1.w, w1.w, d1);
            d2 = __dp4a(q2.x, w2.x, d2); d2 = __dp4a(q2.y, w2.y, d2);
            d2 = __dp4a(q2.z, w2.z, d2); d2 = __dp4a(q2.w, w2.w, d2);
            d3 = __dp4a(q3.x, w3.x, d3); d3 = __dp4a(q3.y, w3.y, d3);
            d3 = __dp4a(q3.z, w3.z, d3); d3 = __dp4a(q3.w, w3.w, d3);
            acc[p] += irow[sx] * (float)((d0 + d1) + (d2 + d3));
        }
    }
    __syncthreads();   // q/inv smem dead from here; stage output (padded stride 129 => conflict-free)

#pragma unroll
    for (int p = 0; p < 32; p++) out_s[co * 129 + pxb + p] = acc[p];
    __syncthreads();

    float wsc = g_wscale;
    for (int it = 0; it < 32; it++) {
        int idx = it * 256 + tid;
        int oc = idx >> 7;
        int px = idx & 127;
        float val = out_s[oc * 129 + px] * wsc + bias[oc];
        out[((size_t)(b * 64 + oc) << 16) + (y << 8) + (x0 + px)] = val;
    }
}

// =====================================================================
// launch
// =====================================================================
extern "C" void kernel_launch(void* const* d_in, const int* in_sizes, int n_in,
                              void* d_out, int out_size) {
    const float* x    = (const float*)d_in[0];
    const float* W    = (const float*)d_in[1];
    const float* bias = (const float*)d_in[2];
    float* out        = (float*)d_out;

    cudaFuncSetAttribute(conv_kernel, cudaFuncAttributeMaxDynamicSharedMemorySize, SMEM_BYTES);

    wquant_kernel<<<1, 1024>>>(W);
    normquant_kernel<<<Bdim * HW / 256, 256>>>(x);
    conv_kernel<<<dim3(Wdim / TW, Hdim, Bdim), 256, SMEM_BYTES>>>(bias, out);
}

// round 6
// speedup vs baseline: 1.4105x; 1.4105x over previous
#include <cuda_runtime.h>
#include <cuda_fp16.h>
#include <cstdint>

// ---------------- problem constants ----------------
#define Bdim 8
#define Cdim 64
#define Hdim 256
#define Wdim 256
#define HW   65536
#define NW   36864              // 64*64*3*3 weight elements

// ---------------- device scratch (no allocs allowed) ----------------
__device__ __half g_y16[(size_t)Bdim * HW * Cdim];   // fp16 y_tilde, NHWC (67 MB)
__device__ __half g_w16[9 * 64 * 64];                // ternary weights fp16, [k9][co][ci]
__device__ float  g_partial[36];
__device__ float  g_wscale;

// ---------------- mma.sync helpers (baseline PTX, works on sm_103) ----
__device__ __forceinline__ uint32_t smem_u32(const void* p) {
    uint32_t a;
    asm("{ .reg .u64 t; cvta.to.shared.u64 t, %1; cvt.u32.u64 %0, t; }" : "=r"(a) : "l"(p));
    return a;
}
__device__ __forceinline__ void ldsm_x4(uint32_t* r, uint32_t addr) {
    asm volatile("ldmatrix.sync.aligned.m8n8.x4.shared.b16 {%0,%1,%2,%3}, [%4];"
                 : "=r"(r[0]), "=r"(r[1]), "=r"(r[2]), "=r"(r[3]) : "r"(addr));
}
__device__ __forceinline__ void mma16816(float* c, const uint32_t* a, const uint32_t* b) {
    asm volatile("mma.sync.aligned.m16n8k16.row.col.f32.f16.f16.f32 "
                 "{%0,%1,%2,%3}, {%4,%5,%6,%7}, {%8,%9}, {%0,%1,%2,%3};"
                 : "+f"(c[0]), "+f"(c[1]), "+f"(c[2]), "+f"(c[3])
                 : "r"(a[0]), "r"(a[1]), "r"(a[2]), "r"(a[3]), "r"(b[0]), "r"(b[1]));
}

// =====================================================================
// Kernel 1a: deterministic |W| partial reduction (36 blocks x 1024)
// =====================================================================
__global__ void __launch_bounds__(1024) wreduce_kernel(const float* __restrict__ W) {
    __shared__ float red[1024];
    int tid = threadIdx.x;
    red[tid] = fabsf(W[blockIdx.x * 1024 + tid]);
    __syncthreads();
    for (int o = 512; o > 0; o >>= 1) {
        if (tid < o) red[tid] += red[tid + o];
        __syncthreads();
    }
    if (tid == 0) g_partial[blockIdx.x] = red[0];
}

// =====================================================================
// Kernel 1b: ternary weight quantization -> fp16 [k9][co][ci]
// =====================================================================
__global__ void __launch_bounds__(1024) wwrite_kernel(const float* __restrict__ W) {
    __shared__ float s_sw;
    if (threadIdx.x == 0) {
        float t = 0.f;
#pragma unroll
        for (int i = 0; i < 36; i++) t += g_partial[i];
        float wsc = fmaxf(t * (1.0f / (float)NW), 1e-8f);
        s_sw = 1.0f / wsc;
        if (blockIdx.x == 0) g_wscale = wsc;
    }
    __syncthreads();
    float sw = s_sw;
    int i = blockIdx.x * 1024 + threadIdx.x;
    float t = fminf(fmaxf(rintf(sw * W[i]), -1.0f), 1.0f);
    int k  = i % 9;          // OIHW: i = (co*64+ci)*9 + k
    int cc = i / 9;
    int ci = cc & 63;
    int co = cc >> 6;
    g_w16[k * 4096 + co * 64 + ci] = __float2half_rn(t);
}

// =====================================================================
// Kernel 2: per-pixel LayerNorm + int8 fake-quant -> fp16 y_tilde NHWC
// =====================================================================
__global__ void __launch_bounds__(256) normquant_kernel(const float* __restrict__ x) {
    int gp = blockIdx.x * 256 + threadIdx.x;
    int b  = gp >> 16;
    int p  = gp & (HW - 1);
    const float* xb = x + (size_t)b * Cdim * HW + p;

    float v[64];
    float sum = 0.f;
#pragma unroll
    for (int c = 0; c < 64; c++) { v[c] = xb[(size_t)c * HW]; sum += v[c]; }
    float mu = sum * (1.0f / 64.0f);

    float sq = 0.f, mx = 0.f;
#pragma unroll
    for (int c = 0; c < 64; c++) {
        float d = v[c] - mu;
        v[c] = d;
        sq += d * d;
        mx = fmaxf(mx, fabsf(d));
    }
    float var  = sq * (1.0f / 64.0f);
    float r    = 1.0f / sqrtf(var + 1e-8f);
    float s    = 127.0f / fmaxf(r * mx, 1e-8f);
    float sr   = s * r;
    float inv  = 1.0f / s;

    uint4* dst = (uint4*)(g_y16 + (size_t)gp * 64);
#pragma unroll
    for (int g = 0; g < 8; g++) {
        unsigned w[4];
#pragma unroll
        for (int h = 0; h < 4; h++) {
            float t0 = fminf(fmaxf(rintf(sr * v[g * 8 + 2 * h]),     -128.f), 127.f) * inv;
            float t1 = fminf(fmaxf(rintf(sr * v[g * 8 + 2 * h + 1]), -128.f), 127.f) * inv;
            __half2 h2 = __floats2half2_rn(t0, t1);
            w[h] = *(unsigned*)&h2;
        }
        dst[g] = make_uint4(w[0], w[1], w[2], w[3]);
    }
}

// =====================================================================
// Kernel 3: conv as implicit-im2col fp16 GEMM via mma.sync (HMMA).
//   Tile: M=256 pixels (2 output rows x 128 px), N=64 co, K=576.
//   A smem: 4 input rows x 130 px x 64 ci fp16 (tap shift folded into
//           per-lane ldmatrix addresses -> no im2col materialization).
//   B smem: [co=64][K=576] fp16.
//   XOR swizzle of 16B chunks (chunk ^= row&7) -> conflict-free ldmatrix.
//   8 warps, warp tile 64m x 32n; 36 K-steps of k16.
// =====================================================================
#define A_PITCH   16640          // 130 px * 128 B
#define A_BYTES   66560          // 4 rows
#define B_OFF     66560
#define B_PITCH   1152           // 576 halves
#define B_BYTES   73728
#define SMEM_DYN  (B_OFF + B_BYTES)   // 140288; out staging (67584 B) overlays A+

__global__ void __launch_bounds__(256, 1) conv_kernel(const float* __restrict__ bias,
                                                      float* __restrict__ out) {
    extern __shared__ char sal[];
    const uint32_t Ab = smem_u32(sal);
    const uint32_t Bb = Ab + B_OFF;

    const int tid  = threadIdx.x;
    const int wid  = tid >> 5;
    const int lane = tid & 31;
    const int wm   = wid & 3;            // m-offset 64*wm
    const int wn   = wid >> 2;           // n-offset 32*wn
    const int b  = blockIdx.z;
    const int y0 = blockIdx.y * 2;
    const int x0 = blockIdx.x * 128;

    // ---- B: weights [k9][co][ci] -> smem [co][k], swizzled 16B chunks ----
    {
        const uint4* gw = (const uint4*)g_w16;
        for (int i = tid; i < 4608; i += 256) {
            int co  = i / 72;
            int c   = i - co * 72;           // k chunk index 0..71
            int tap = c >> 3;
            int j   = c & 7;
            uint4 v = gw[tap * 512 + co * 8 + j];
            uint32_t sc = (uint32_t)((c & ~7) | ((c & 7) ^ (co & 7)));
            *(uint4*)(sal + B_OFF + co * B_PITCH + (sc << 4)) = v;
        }
    }
    // ---- A: 4 input rows x 130 px x 64 ci, zero-padded, swizzled ----
    {
        const uint4* gy = (const uint4*)g_y16;
        for (int i = tid; i < 4160; i += 256) {
            int irow = i / 1040;
            int rem  = i - irow * 1040;
            int px   = rem >> 3;
            int j    = rem & 7;
            int ys = y0 + irow - 1;
            int xs = x0 + px - 1;
            uint4 v = make_uint4(0, 0, 0, 0);
            if ((unsigned)ys < 256u && (unsigned)xs < 256u)
                v = gy[(size_t)((b << 16) + (ys << 8) + xs) * 8 + j];
            *(uint4*)(sal + irow * A_PITCH + px * 128 + ((j ^ (px & 7)) << 4)) = v;
        }
    }
    __syncthreads();

    // ---- mainloop: 36 K-steps ----
    float acc[4][4][4];
#pragma unroll
    for (int i = 0; i < 4; i++)
#pragma unroll
        for (int jn = 0; jn < 4; jn++)
#pragma unroll
            for (int e = 0; e < 4; e++) acc[i][jn][e] = 0.f;

    const int a_ml    = lane & 15;       // m within m16 tile
    const int a_kh    = lane >> 4;       // k half (0/1)
    const int b_nl    = (lane & 7) | ((lane >> 4) << 3);
    const int b_kh    = (lane >> 3) & 1;

#pragma unroll 1
    for (int s = 0; s < 36; s++) {
        int tap = s >> 2, kc = s & 3;
        int rr  = (tap * 11) >> 5;       // tap/3 for tap<9
        int dx  = tap - rr * 3;

        uint32_t av[4][4];
#pragma unroll
        for (int tmi = 0; tmi < 4; tmi++) {
            int m    = wm * 64 + tmi * 16 + a_ml;
            int p    = (m & 127) + dx;
            int irow = (m >> 7) + rr;
            uint32_t addr = Ab + irow * A_PITCH + p * 128
                          + (uint32_t)((((kc << 1) | a_kh) ^ (p & 7)) << 4);
            ldsm_x4(av[tmi], addr);
        }
        uint32_t bv[4][2];
#pragma unroll
        for (int tb = 0; tb < 2; tb++) {
            int co = wn * 32 + tb * 16 + b_nl;
            int c  = (s << 1) | b_kh;
            uint32_t sc = (uint32_t)((c & ~7) | ((c & 7) ^ (co & 7)));
            uint32_t r[4];
            ldsm_x4(r, Bb + co * B_PITCH + (sc << 4));
            bv[tb * 2][0] = r[0]; bv[tb * 2][1] = r[1];
            bv[tb * 2 + 1][0] = r[2]; bv[tb * 2 + 1][1] = r[3];
        }
#pragma unroll
        for (int tmi = 0; tmi < 4; tmi++)
#pragma unroll
            for (int tni = 0; tni < 4; tni++)
                mma16816(acc[tmi][tni], av[tmi], bv[tni]);
    }
    __syncthreads();   // A/B smem dead; reuse for output staging

    // ---- stage accs: [co][px] pitch 264 floats (conflict-free STS) ----
    float* stage = (float*)sal;
    const int pxb = wm * 64 + (lane >> 2);
    const int cob = wn * 32 + 2 * (lane & 3);
#pragma unroll
    for (int tmi = 0; tmi < 4; tmi++)
#pragma unroll
        for (int tni = 0; tni < 4; tni++) {
            int px = pxb + tmi * 16;
            int co = cob + tni * 8;
            stage[co * 264 + px]            = acc[tmi][tni][0];
            stage[(co + 1) * 264 + px]      = acc[tmi][tni][1];
            stage[co * 264 + px + 8]        = acc[tmi][tni][2];
            stage[(co + 1) * 264 + px + 8]  = acc[tmi][tni][3];
        }
    __syncthreads();

    // ---- coalesced NCHW store ----
    float wsc = g_wscale;
    for (int it = 0; it < 64; it++) {
        int idx = it * 256 + tid;
        int co  = idx >> 8;
        int px  = idx & 255;
        float val = fmaf(stage[co * 264 + px], wsc, __ldg(&bias[co]));
        out[(((size_t)(b * 64 + co)) << 16) + ((y0 + (px >> 7)) << 8) + (x0 + (px & 127))] = val;
    }
}

// =====================================================================
// launch
// =====================================================================
extern "C" void kernel_launch(void* const* d_in, const int* in_sizes, int n_in,
                              void* d_out, int out_size) {
    const float* x    = (const float*)d_in[0];
    const float* W    = (const float*)d_in[1];
    const float* bias = (const float*)d_in[2];
    float* out        = (float*)d_out;

    cudaFuncSetAttribute(conv_kernel, cudaFuncAttributeMaxDynamicSharedMemorySize, SMEM_DYN);

    wreduce_kernel<<<36, 1024>>>(W);
    wwrite_kernel<<<36, 1024>>>(W);
    normquant_kernel<<<Bdim * HW / 256, 256>>>(x);
    conv_kernel<<<dim3(2, 128, Bdim), 256, SMEM_DYN>>>(bias, out);
}